// round 16
// baseline (speedup 1.0000x reference)
#include <cuda_runtime.h>
#include <cuda_bf16.h>
#include <cstdint>

// Problem constants
#define PN 8192      // batch rows
#define PC 1024      // feature dim
#define PS 8192      // negatives (sampled)
#define PUNITS 128000

// ---------------- device scratch (static, allocation-free) ----------------
__device__ __nv_bfloat16 g_X[PN * PC];   // inputs in bf16           (16 MB)
__device__ __nv_bfloat16 g_W[PS * PC];   // gathered sampled rows    (16 MB)
__device__ float g_bcorr[PS];            // bias[sampled] - log(E(sampled))
__device__ float g_true[PN];             // corrected true logits
__device__ float g_rowsum[PN];           // sum_s exp(corrected samp logit)
__device__ double g_part[64];            // finalize block partials
__device__ unsigned int g_tick;          // finalize ticket counter

// ---------------- helpers ----------------
__device__ __forceinline__ float neg_log_expected(int id) {
    float idf = (float)id;
    float p = (logf(idf + 2.0f) - logf(idf + 1.0f)) / logf((float)(PUNITS + 1));
    float e = -expm1f((float)PS * log1pf(-p));
    return -logf(e);
}

__device__ __forceinline__ uint32_t pack_bf2(float a, float b) {
    __nv_bfloat162 v = __floats2bfloat162_rn(a, b);
    uint32_t u;
    memcpy(&u, &v, 4);
    return u;
}

__device__ __forceinline__ uint4 pack8(const float4 v0, const float4 v1) {
    uint4 r;
    r.x = pack_bf2(v0.x, v0.y);
    r.y = pack_bf2(v0.z, v0.w);
    r.z = pack_bf2(v1.x, v1.y);
    r.w = pack_bf2(v1.z, v1.w);
    return r;
}

__device__ __forceinline__ void ldm_x4(uint32_t (&r)[4], uint32_t saddr) {
    asm volatile("ldmatrix.sync.aligned.m8n8.x4.shared.b16 {%0,%1,%2,%3}, [%4];"
                 : "=r"(r[0]), "=r"(r[1]), "=r"(r[2]), "=r"(r[3])
                 : "r"(saddr));
}

__device__ __forceinline__ void mma_bf16(float (&c)[4], const uint32_t (&a)[4],
                                         const uint32_t b0, const uint32_t b1) {
    asm volatile(
        "mma.sync.aligned.m16n8k16.row.col.f32.bf16.bf16.f32 "
        "{%0,%1,%2,%3}, {%4,%5,%6,%7}, {%8,%9}, {%0,%1,%2,%3};"
        : "+f"(c[0]), "+f"(c[1]), "+f"(c[2]), "+f"(c[3])
        : "r"(a[0]), "r"(a[1]), "r"(a[2]), "r"(a[3]), "r"(b0), "r"(b1));
}

#define CP_ASYNC16(dst, src) \
    asm volatile("cp.async.cg.shared.global [%0], [%1], 16;" :: "r"(dst), "l"(src))

// ---------------- prep: convert + gather + bcorr + true logits (fused) -------
#define HALF4 ((PN * PC) / 8 / 2)      // 524288: chunk count per half

__global__ void prep_kernel(const float* __restrict__ inputs,
                            const int* __restrict__ sampled,
                            const int* __restrict__ targets,
                            const float* __restrict__ kern,
                            const float* __restrict__ bias) {
    const int gid = blockIdx.x * blockDim.x + threadIdx.x;
    if (gid == 0) g_tick = 0;

    const int i0 = gid;
    const int i1 = gid + HALF4;

    const int s0 = i0 >> 7, s1 = i1 >> 7;
    const int sid0 = sampled[s0];
    const int sid1 = sampled[s1];

    const float4* xp0 = (const float4*)inputs + 2 * i0;
    const float4* xp1 = (const float4*)inputs + 2 * i1;
    float4 x00 = xp0[0], x01 = xp0[1];
    float4 x10 = xp1[0], x11 = xp1[1];

    const int c0 = i0 & 127, c1 = i1 & 127;
    const float4* wp0 = (const float4*)(kern + ((size_t)sid0 << 10)) + 2 * c0;
    const float4* wp1 = (const float4*)(kern + ((size_t)sid1 << 10)) + 2 * c1;
    float4 w00 = wp0[0], w01 = wp0[1];
    float4 w10 = wp1[0], w11 = wp1[1];

    ((uint4*)g_X)[i0] = pack8(x00, x01);
    ((uint4*)g_X)[i1] = pack8(x10, x11);
    ((uint4*)g_W)[i0] = pack8(w00, w01);
    ((uint4*)g_W)[i1] = pack8(w10, w11);

    if (gid < PS) {
        int sid = sampled[gid];
        g_bcorr[gid] = bias[sid] + neg_log_expected(sid);
    }

    // true logits: blocks 0..PN/8-1 compute 8 rows each (one per warp)
    if (blockIdx.x < PN / 8) {
        int warp = threadIdx.x >> 5, lane = threadIdx.x & 31;
        int n = blockIdx.x * 8 + warp;
        int tgt = targets[n];
        const float4* xr = (const float4*)(inputs + ((size_t)n << 10));
        const float4* wr = (const float4*)(kern + ((size_t)tgt << 10));
        float d = 0.f;
#pragma unroll
        for (int it = 0; it < 8; ++it) {
            float4 a = xr[lane + it * 32];
            float4 b = wr[lane + it * 32];
            d += a.x * b.x + a.y * b.y + a.z * b.z + a.w * b.w;
        }
#pragma unroll
        for (int o = 16; o; o >>= 1) d += __shfl_down_sync(0xffffffffu, d, o);
        if (lane == 0) {
            g_true[n] = d + bias[tgt] + neg_log_expected(tgt);
            g_rowsum[n] = 0.f;
        }
    }
}

// ---------------- fused GEMM (bf16 mma.sync) + exp epilogue ----------------
// CTA tile 128x128, 4 warps in 2(M) x 2(N), warp tile 64x64.
// K-chunk 64, 3-stage cp.async pipeline, register fragment double-buffering,
// FINE-GRAINED interleave: each ks-phase emits 8 subgroups of
// [1 ldmatrix -> (1 cp.async) -> 4 MMAs] so the tensor pipe never starves.
#define SLD 72                         // smem K stride (64 + 8 pad) in bf16
#define A_STG (128 * SLD * 2)          // 18432 B per operand stage
#define NSTG 3
#define OFF_B    (NSTG * A_STG)        // 55296
#define OFF_SROW (2 * NSTG * A_STG)    // 110592
#define SMEM_BYTES (OFF_SROW + 512)
#define NK (PC / 64)                   // 16 K-chunks

__global__ __launch_bounds__(128, 2) void gemm_exp_kernel(
    const int* __restrict__ targets, const int* __restrict__ sampled) {
    extern __shared__ char smem[];
    float* srow = (float*)(smem + OFF_SROW);

    const int tid = threadIdx.x;
    const int lane = tid & 31, warp = tid >> 5;
    const int wm = warp >> 1, wn = warp & 1;       // 2 x 2 warp grid
    const int bm = blockIdx.y * 128, bn = blockIdx.x * 128;

    float acc[4][8][4];
#pragma unroll
    for (int mi = 0; mi < 4; mi++)
#pragma unroll
        for (int ni = 0; ni < 8; ni++)
#pragma unroll
            for (int e = 0; e < 4; e++) acc[mi][ni][e] = 0.f;

    srow[tid] = 0.f;

    uint32_t sbase;
    asm("{ .reg .u64 t; cvta.to.shared.u64 t, %1; cvt.u32.u64 %0, t; }"
        : "=r"(sbase) : "l"(smem));
    const uint32_t sA = sbase;
    const uint32_t sB = sbase + OFF_B;

    // ldmatrix per-lane address components (within tile)
    const int arow  = wm * 64 + (lane & 7) + 8 * ((lane >> 3) & 1);
    const int acoff = (lane >> 4) * 8;
    const int brow  = wn * 64 + (lane & 7) + 8 * (lane >> 4);
    const int bcoff = ((lane >> 3) & 1) * 8;

    // global->shared: 1024 16B chunks per operand per stage, 8 per thread
    const int r0 = tid >> 3, c0 = tid & 7;   // rows r0 + it*16, it=0..7
    const __nv_bfloat16* Ag = g_X + (size_t)(bm + r0) * PC + c0 * 8;
    const __nv_bfloat16* Bg = g_W + (size_t)(bn + r0) * PC + c0 * 8;
    const uint32_t dA = sA + (uint32_t)(r0 * SLD + c0 * 8) * 2;
    const uint32_t dB = sB + (uint32_t)(r0 * SLD + c0 * 8) * 2;

#define LOAD_STAGE(kt_, so_)                                                   \
    do {                                                                       \
        if ((kt_) < NK) {                                                      \
            uint32_t so = (uint32_t)(so_) * A_STG;                             \
            int ko = (kt_) * 64;                                               \
            _Pragma("unroll")                                                  \
            for (int it = 0; it < 8; ++it) {                                   \
                CP_ASYNC16(dA + so + (uint32_t)(it * 16 * SLD * 2),            \
                           Ag + ko + (size_t)it * 16 * PC);                    \
                CP_ASYNC16(dB + so + (uint32_t)(it * 16 * SLD * 2),            \
                           Bg + ko + (size_t)it * 16 * PC);                    \
            }                                                                  \
        }                                                                      \
        asm volatile("cp.async.commit_group;" ::: "memory");                   \
    } while (0)

    uint32_t afr[2][4][4];
    uint32_t bfr[2][8][2];

#define LDFRAG(buf_, ca_, cb_, ks_)                                            \
    do {                                                                       \
        _Pragma("unroll")                                                      \
        for (int mi = 0; mi < 4; mi++)                                         \
            ldm_x4(afr[buf_][mi], (ca_) +                                      \
                (uint32_t)(((arow + mi * 16) * SLD + (ks_) * 16 + acoff) * 2));\
        _Pragma("unroll")                                                      \
        for (int nb = 0; nb < 4; nb++) {                                       \
            uint32_t r[4];                                                     \
            ldm_x4(r, (cb_) +                                                  \
                (uint32_t)(((brow + nb * 16) * SLD + (ks_) * 16 + bcoff) * 2));\
            bfr[buf_][2 * nb][0] = r[0];                                       \
            bfr[buf_][2 * nb][1] = r[1];                                       \
            bfr[buf_][2 * nb + 1][0] = r[2];                                   \
            bfr[buf_][2 * nb + 1][1] = r[3];                                   \
        }                                                                      \
    } while (0)

// One ks-phase: 32 MMAs on buffer mb_; optionally load next fragments into
// lb_ (8 ldmatrix) and issue quarter q_ of next-stage cp.async (4 ops) —
// all interleaved in 8 subgroups of [ldm, (cp), 4x mma].
#define PHASE(mb_, lb_, do_ld_, ca_, cb_, ksn_, do_cp_, so_, ko_, q_)          \
    do {                                                                       \
        _Pragma("unroll")                                                      \
        for (int g = 0; g < 8; ++g) {                                          \
            if (do_ld_) {                                                      \
                if (g < 4) {                                                   \
                    ldm_x4(afr[lb_][g], (ca_) + (uint32_t)(                    \
                        ((arow + g * 16) * SLD + (ksn_) * 16 + acoff) * 2));   \
                } else {                                                       \
                    const int nb = g - 4;                                      \
                    uint32_t r[4];                                             \
                    ldm_x4(r, (cb_) + (uint32_t)(                              \
                        ((brow + nb * 16) * SLD + (ksn_) * 16 + bcoff) * 2));  \
                    bfr[lb_][2 * nb][0] = r[0];                                \
                    bfr[lb_][2 * nb][1] = r[1];                                \
                    bfr[lb_][2 * nb + 1][0] = r[2];                            \
                    bfr[lb_][2 * nb + 1][1] = r[3];                            \
                }                                                              \
            }                                                                  \
            if ((do_cp_) && (g & 1)) {                                         \
                const int idx = g >> 1;             /* 0..3 */                 \
                const int it = (q_) * 2 + (idx & 1); /* rows 2q, 2q+1 */       \
                if (idx < 2)                                                   \
                    CP_ASYNC16(dA + (so_) + (uint32_t)(it * 16 * SLD * 2),     \
                               Ag + (ko_) + (size_t)it * 16 * PC);             \
                else                                                           \
                    CP_ASYNC16(dB + (so_) + (uint32_t)(it * 16 * SLD * 2),     \
                               Bg + (ko_) + (size_t)it * 16 * PC);             \
            }                                                                  \
            const int mi_ = g >> 1;                                            \
            const int nb_ = (g & 1) * 4;                                       \
            _Pragma("unroll")                                                  \
            for (int ni = nb_; ni < nb_ + 4; ++ni)                             \
                mma_bf16(acc[mi_][ni], afr[mb_][mi_], bfr[mb_][ni][0],         \
                         bfr[mb_][ni][1]);                                     \
        }                                                                      \
    } while (0)

    // prologue: stages 0,1 in flight; stage 0 ready; preload ks=0 fragments
    LOAD_STAGE(0, 0);
    LOAD_STAGE(1, 1);
    asm volatile("cp.async.wait_group 1;" ::: "memory");
    __syncthreads();

    int s_cur = 0, s_ld = 2;
    uint32_t ca = sA, cb = sB;
    LDFRAG(0, ca, cb, 0);

#pragma unroll 1
    for (int kt = 0; kt < NK; ++kt) {
        const bool docp = (kt + 2) < NK;
        const uint32_t so = (uint32_t)s_ld * A_STG;
        const int ko = (kt + 2) * 64;

        PHASE(0, 1, true,  ca, cb, 1, docp, so, ko, 0);
        PHASE(1, 0, true,  ca, cb, 2, docp, so, ko, 1);
        PHASE(0, 1, true,  ca, cb, 3, docp, so, ko, 2);
        PHASE(1, 0, false, ca, cb, 0, docp, so, ko, 3);
        asm volatile("cp.async.commit_group;" ::: "memory");

        s_ld = (s_ld == 2) ? 0 : s_ld + 1;

        if (kt + 1 < NK) {
            asm volatile("cp.async.wait_group 1;" ::: "memory");
            __syncthreads();
            s_cur = (s_cur == 2) ? 0 : s_cur + 1;
            ca = sA + (uint32_t)s_cur * A_STG;
            cb = sB + (uint32_t)s_cur * A_STG;
            LDFRAG(0, ca, cb, 0);
        }
    }

    // ---- epilogue: corrected logits -> exp -> per-row partial sums ----
    int tg[4][2];
#pragma unroll
    for (int mi = 0; mi < 4; mi++)
#pragma unroll
        for (int h = 0; h < 2; h++)
            tg[mi][h] = targets[bm + wm * 64 + mi * 16 + (lane >> 2) + h * 8];

    float rs[4][2];
#pragma unroll
    for (int mi = 0; mi < 4; mi++) { rs[mi][0] = 0.f; rs[mi][1] = 0.f; }

#pragma unroll
    for (int ni = 0; ni < 8; ni++) {
#pragma unroll
        for (int j = 0; j < 2; j++) {
            int col = bn + wn * 64 + ni * 8 + ((lane & 3) << 1) + j;
            int sid = sampled[col];
            float bc = g_bcorr[col];
#pragma unroll
            for (int mi = 0; mi < 4; mi++) {
#pragma unroll
                for (int h = 0; h < 2; h++) {
                    if (sid != tg[mi][h])
                        rs[mi][h] += __expf(acc[mi][ni][h * 2 + j] + bc);
                }
            }
        }
    }

#pragma unroll
    for (int mi = 0; mi < 4; mi++) {
#pragma unroll
        for (int h = 0; h < 2; h++) {
            float v = rs[mi][h];
            v += __shfl_xor_sync(0xffffffffu, v, 1);
            v += __shfl_xor_sync(0xffffffffu, v, 2);
            if ((lane & 3) == 0)
                atomicAdd(&srow[wm * 64 + mi * 16 + (lane >> 2) + h * 8], v);
        }
    }
    __syncthreads();
    atomicAdd(&g_rowsum[bm + tid], srow[tid]);
}

// ---------------- finalize: parallel per-example loss + mean ----------------
__global__ void finalize_kernel(float* __restrict__ out) {
    __shared__ double sh[4];
    const int n = blockIdx.x * 128 + threadIdx.x;
    const int lane = threadIdx.x & 31, wid = threadIdx.x >> 5;

    float t = g_true[n];
    double local = (double)(logf(g_rowsum[n] + expf(t)) - t);
#pragma unroll
    for (int o = 16; o; o >>= 1) local += __shfl_down_sync(0xffffffffu, local, o);
    if (lane == 0) sh[wid] = local;
    __syncthreads();
    if (threadIdx.x == 0) {
        double s = sh[0] + sh[1] + sh[2] + sh[3];
        g_part[blockIdx.x] = s;
        __threadfence();
        unsigned int r = atomicAdd(&g_tick, 1u);
        if (r == 63u) {
            double tot = 0.0;
#pragma unroll 8
            for (int i = 0; i < 64; ++i) tot += g_part[i];
            out[0] = (float)(tot / (double)PN);
        }
    }
}

// ---------------- entry ----------------
extern "C" void kernel_launch(void* const* d_in, const int* in_sizes, int n_in,
                              void* d_out, int out_size) {
    const float* inputs  = (const float*)d_in[0];
    const int*   targets = (const int*)d_in[1];
    const int*   sampled = (const int*)d_in[2];
    const float* kern    = (const float*)d_in[3];
    const float* bias    = (const float*)d_in[4];
    float* out = (float*)d_out;

    static int smem_set = 0;
    if (!smem_set) {
        cudaFuncSetAttribute(gemm_exp_kernel,
                             cudaFuncAttributeMaxDynamicSharedMemorySize, SMEM_BYTES);
        smem_set = 1;
    }

    prep_kernel<<<2048, 256>>>(inputs, sampled, targets, kern, bias);

    dim3 grid(PS / 128, PN / 128);
    gemm_exp_kernel<<<grid, 128, SMEM_BYTES>>>(targets, sampled);

    finalize_kernel<<<64, 128>>>(out);
}

// round 17
// speedup vs baseline: 1.0016x; 1.0016x over previous
#include <cuda_runtime.h>
#include <cuda_bf16.h>
#include <cstdint>

// Problem constants
#define PN 8192      // batch rows
#define PC 1024      // feature dim
#define PS 8192      // negatives (sampled)
#define PUNITS 128000

// ---------------- device scratch (static, allocation-free) ----------------
__device__ __nv_bfloat16 g_X[PN * PC];   // inputs in bf16           (16 MB)
__device__ __nv_bfloat16 g_W[PS * PC];   // gathered sampled rows    (16 MB)
__device__ float g_bcorr[PS];            // bias[sampled] - log(E(sampled))
__device__ float g_true[PN];             // corrected true logits
__device__ float g_rowsum[PN];           // sum_s exp(corrected samp logit)
__device__ double g_part[64];            // finalize block partials
__device__ unsigned int g_tick;          // finalize ticket counter

// ---------------- helpers ----------------
__device__ __forceinline__ float neg_log_expected(int id) {
    float idf = (float)id;
    float p = (logf(idf + 2.0f) - logf(idf + 1.0f)) / logf((float)(PUNITS + 1));
    float e = -expm1f((float)PS * log1pf(-p));
    return -logf(e);
}

__device__ __forceinline__ uint32_t pack_bf2(float a, float b) {
    __nv_bfloat162 v = __floats2bfloat162_rn(a, b);
    uint32_t u;
    memcpy(&u, &v, 4);
    return u;
}

__device__ __forceinline__ uint4 pack8(const float4 v0, const float4 v1) {
    uint4 r;
    r.x = pack_bf2(v0.x, v0.y);
    r.y = pack_bf2(v0.z, v0.w);
    r.z = pack_bf2(v1.x, v1.y);
    r.w = pack_bf2(v1.z, v1.w);
    return r;
}

__device__ __forceinline__ void ldm_x4(uint32_t (&r)[4], uint32_t saddr) {
    asm volatile("ldmatrix.sync.aligned.m8n8.x4.shared.b16 {%0,%1,%2,%3}, [%4];"
                 : "=r"(r[0]), "=r"(r[1]), "=r"(r[2]), "=r"(r[3])
                 : "r"(saddr));
}

__device__ __forceinline__ void mma_bf16(float (&c)[4], const uint32_t (&a)[4],
                                         const uint32_t b0, const uint32_t b1) {
    asm volatile(
        "mma.sync.aligned.m16n8k16.row.col.f32.bf16.bf16.f32 "
        "{%0,%1,%2,%3}, {%4,%5,%6,%7}, {%8,%9}, {%0,%1,%2,%3};"
        : "+f"(c[0]), "+f"(c[1]), "+f"(c[2]), "+f"(c[3])
        : "r"(a[0]), "r"(a[1]), "r"(a[2]), "r"(a[3]), "r"(b0), "r"(b1));
}

#define CP_ASYNC16(dst, src) \
    asm volatile("cp.async.cg.shared.global [%0], [%1], 16;" :: "r"(dst), "l"(src))

// ---------------- prep: convert + gather + bcorr + true logits (fused) -------
#define HALF4 ((PN * PC) / 8 / 2)      // 524288: chunk count per half

__global__ void prep_kernel(const float* __restrict__ inputs,
                            const int* __restrict__ sampled,
                            const int* __restrict__ targets,
                            const float* __restrict__ kern,
                            const float* __restrict__ bias) {
    const int gid = blockIdx.x * blockDim.x + threadIdx.x;
    if (gid == 0) g_tick = 0;

    const int i0 = gid;
    const int i1 = gid + HALF4;

    const int s0 = i0 >> 7, s1 = i1 >> 7;
    const int sid0 = sampled[s0];
    const int sid1 = sampled[s1];

    const float4* xp0 = (const float4*)inputs + 2 * i0;
    const float4* xp1 = (const float4*)inputs + 2 * i1;
    float4 x00 = xp0[0], x01 = xp0[1];
    float4 x10 = xp1[0], x11 = xp1[1];

    const int c0 = i0 & 127, c1 = i1 & 127;
    const float4* wp0 = (const float4*)(kern + ((size_t)sid0 << 10)) + 2 * c0;
    const float4* wp1 = (const float4*)(kern + ((size_t)sid1 << 10)) + 2 * c1;
    float4 w00 = wp0[0], w01 = wp0[1];
    float4 w10 = wp1[0], w11 = wp1[1];

    ((uint4*)g_X)[i0] = pack8(x00, x01);
    ((uint4*)g_X)[i1] = pack8(x10, x11);
    ((uint4*)g_W)[i0] = pack8(w00, w01);
    ((uint4*)g_W)[i1] = pack8(w10, w11);

    if (gid < PS) {
        int sid = sampled[gid];
        g_bcorr[gid] = bias[sid] + neg_log_expected(sid);
    }

    // true logits: blocks 0..PN/8-1 compute 8 rows each (one per warp)
    if (blockIdx.x < PN / 8) {
        int warp = threadIdx.x >> 5, lane = threadIdx.x & 31;
        int n = blockIdx.x * 8 + warp;
        int tgt = targets[n];
        const float4* xr = (const float4*)(inputs + ((size_t)n << 10));
        const float4* wr = (const float4*)(kern + ((size_t)tgt << 10));
        float d = 0.f;
#pragma unroll
        for (int it = 0; it < 8; ++it) {
            float4 a = xr[lane + it * 32];
            float4 b = wr[lane + it * 32];
            d += a.x * b.x + a.y * b.y + a.z * b.z + a.w * b.w;
        }
#pragma unroll
        for (int o = 16; o; o >>= 1) d += __shfl_down_sync(0xffffffffu, d, o);
        if (lane == 0) {
            g_true[n] = d + bias[tgt] + neg_log_expected(tgt);
            g_rowsum[n] = 0.f;
        }
    }
}

// ---------------- fused GEMM (bf16 mma.sync) + exp epilogue ----------------
// CTA tile 128x128, 4 warps in 2(M) x 2(N), warp tile 64x64.
// K-chunk 64, 3-stage cp.async pipeline, register fragment double-buffering,
// FINE-GRAINED interleave: each ks-phase emits 8 subgroups of
// [1 ldmatrix -> (1 cp.async) -> 4 MMAs] so the tensor pipe never starves.
#define SLD 72                         // smem K stride (64 + 8 pad) in bf16
#define A_STG (128 * SLD * 2)          // 18432 B per operand stage
#define NSTG 3
#define OFF_B    (NSTG * A_STG)        // 55296
#define OFF_SROW (2 * NSTG * A_STG)    // 110592
#define SMEM_BYTES (OFF_SROW + 512)
#define NK (PC / 64)                   // 16 K-chunks

__global__ __launch_bounds__(128, 2) void gemm_exp_kernel(
    const int* __restrict__ targets, const int* __restrict__ sampled) {
    extern __shared__ char smem[];
    float* srow = (float*)(smem + OFF_SROW);

    const int tid = threadIdx.x;
    const int lane = tid & 31, warp = tid >> 5;
    const int wm = warp >> 1, wn = warp & 1;       // 2 x 2 warp grid
    const int bm = blockIdx.y * 128, bn = blockIdx.x * 128;

    float acc[4][8][4];
#pragma unroll
    for (int mi = 0; mi < 4; mi++)
#pragma unroll
        for (int ni = 0; ni < 8; ni++)
#pragma unroll
            for (int e = 0; e < 4; e++) acc[mi][ni][e] = 0.f;

    srow[tid] = 0.f;

    uint32_t sbase;
    asm("{ .reg .u64 t; cvta.to.shared.u64 t, %1; cvt.u32.u64 %0, t; }"
        : "=r"(sbase) : "l"(smem));
    const uint32_t sA = sbase;
    const uint32_t sB = sbase + OFF_B;

    // ldmatrix per-lane address components (within tile)
    const int arow  = wm * 64 + (lane & 7) + 8 * ((lane >> 3) & 1);
    const int acoff = (lane >> 4) * 8;
    const int brow  = wn * 64 + (lane & 7) + 8 * (lane >> 4);
    const int bcoff = ((lane >> 3) & 1) * 8;

    // global->shared: 1024 16B chunks per operand per stage, 8 per thread
    const int r0 = tid >> 3, c0 = tid & 7;   // rows r0 + it*16, it=0..7
    const __nv_bfloat16* Ag = g_X + (size_t)(bm + r0) * PC + c0 * 8;
    const __nv_bfloat16* Bg = g_W + (size_t)(bn + r0) * PC + c0 * 8;
    const uint32_t dA = sA + (uint32_t)(r0 * SLD + c0 * 8) * 2;
    const uint32_t dB = sB + (uint32_t)(r0 * SLD + c0 * 8) * 2;

#define LOAD_STAGE(kt_, so_)                                                   \
    do {                                                                       \
        if ((kt_) < NK) {                                                      \
            uint32_t so = (uint32_t)(so_) * A_STG;                             \
            int ko = (kt_) * 64;                                               \
            _Pragma("unroll")                                                  \
            for (int it = 0; it < 8; ++it) {                                   \
                CP_ASYNC16(dA + so + (uint32_t)(it * 16 * SLD * 2),            \
                           Ag + ko + (size_t)it * 16 * PC);                    \
                CP_ASYNC16(dB + so + (uint32_t)(it * 16 * SLD * 2),            \
                           Bg + ko + (size_t)it * 16 * PC);                    \
            }                                                                  \
        }                                                                      \
        asm volatile("cp.async.commit_group;" ::: "memory");                   \
    } while (0)

    uint32_t afr[2][4][4];
    uint32_t bfr[2][8][2];

#define LDFRAG(buf_, ca_, cb_, ks_)                                            \
    do {                                                                       \
        _Pragma("unroll")                                                      \
        for (int mi = 0; mi < 4; mi++)                                         \
            ldm_x4(afr[buf_][mi], (ca_) +                                      \
                (uint32_t)(((arow + mi * 16) * SLD + (ks_) * 16 + acoff) * 2));\
        _Pragma("unroll")                                                      \
        for (int nb = 0; nb < 4; nb++) {                                       \
            uint32_t r[4];                                                     \
            ldm_x4(r, (cb_) +                                                  \
                (uint32_t)(((brow + nb * 16) * SLD + (ks_) * 16 + bcoff) * 2));\
            bfr[buf_][2 * nb][0] = r[0];                                       \
            bfr[buf_][2 * nb][1] = r[1];                                       \
            bfr[buf_][2 * nb + 1][0] = r[2];                                   \
            bfr[buf_][2 * nb + 1][1] = r[3];                                   \
        }                                                                      \
    } while (0)

// One ks-phase: 32 MMAs on buffer mb_; optionally load next fragments into
// lb_ (8 ldmatrix) and issue quarter q_ of next-stage cp.async (4 ops) —
// all interleaved in 8 subgroups of [ldm, (cp), 4x mma].
#define PHASE(mb_, lb_, do_ld_, ca_, cb_, ksn_, do_cp_, so_, ko_, q_)          \
    do {                                                                       \
        _Pragma("unroll")                                                      \
        for (int g = 0; g < 8; ++g) {                                          \
            if (do_ld_) {                                                      \
                if (g < 4) {                                                   \
                    ldm_x4(afr[lb_][g], (ca_) + (uint32_t)(                    \
                        ((arow + g * 16) * SLD + (ksn_) * 16 + acoff) * 2));   \
                } else {                                                       \
                    const int nb = g - 4;                                      \
                    uint32_t r[4];                                             \
                    ldm_x4(r, (cb_) + (uint32_t)(                              \
                        ((brow + nb * 16) * SLD + (ksn_) * 16 + bcoff) * 2));  \
                    bfr[lb_][2 * nb][0] = r[0];                                \
                    bfr[lb_][2 * nb][1] = r[1];                                \
                    bfr[lb_][2 * nb + 1][0] = r[2];                            \
                    bfr[lb_][2 * nb + 1][1] = r[3];                            \
                }                                                              \
            }                                                                  \
            if ((do_cp_) && (g & 1)) {                                         \
                const int idx = g >> 1;             /* 0..3 */                 \
                const int it = (q_) * 2 + (idx & 1); /* rows 2q, 2q+1 */       \
                if (idx < 2)                                                   \
                    CP_ASYNC16(dA + (so_) + (uint32_t)(it * 16 * SLD * 2),     \
                               Ag + (ko_) + (size_t)it * 16 * PC);             \
                else                                                           \
                    CP_ASYNC16(dB + (so_) + (uint32_t)(it * 16 * SLD * 2),     \
                               Bg + (ko_) + (size_t)it * 16 * PC);             \
            }                                                                  \
            const int mi_ = g >> 1;                                            \
            const int nb_ = (g & 1) * 4;                                       \
            _Pragma("unroll")                                                  \
            for (int ni = nb_; ni < nb_ + 4; ++ni)                             \
                mma_bf16(acc[mi_][ni], afr[mb_][mi_], bfr[mb_][ni][0],         \
                         bfr[mb_][ni][1]);                                     \
        }                                                                      \
    } while (0)

    // prologue: stages 0,1 in flight; stage 0 ready; preload ks=0 fragments
    LOAD_STAGE(0, 0);
    LOAD_STAGE(1, 1);
    asm volatile("cp.async.wait_group 1;" ::: "memory");
    __syncthreads();

    int s_cur = 0, s_ld = 2;
    uint32_t ca = sA, cb = sB;
    LDFRAG(0, ca, cb, 0);

#pragma unroll 1
    for (int kt = 0; kt < NK; ++kt) {
        const bool docp = (kt + 2) < NK;
        const uint32_t so = (uint32_t)s_ld * A_STG;
        const int ko = (kt + 2) * 64;

        PHASE(0, 1, true,  ca, cb, 1, docp, so, ko, 0);
        PHASE(1, 0, true,  ca, cb, 2, docp, so, ko, 1);
        PHASE(0, 1, true,  ca, cb, 3, docp, so, ko, 2);
        PHASE(1, 0, false, ca, cb, 0, docp, so, ko, 3);
        asm volatile("cp.async.commit_group;" ::: "memory");

        s_ld = (s_ld == 2) ? 0 : s_ld + 1;

        if (kt + 1 < NK) {
            asm volatile("cp.async.wait_group 1;" ::: "memory");
            __syncthreads();
            s_cur = (s_cur == 2) ? 0 : s_cur + 1;
            ca = sA + (uint32_t)s_cur * A_STG;
            cb = sB + (uint32_t)s_cur * A_STG;
            LDFRAG(0, ca, cb, 0);
        }
    }

    // ---- epilogue: corrected logits -> exp -> per-row partial sums ----
    int tg[4][2];
#pragma unroll
    for (int mi = 0; mi < 4; mi++)
#pragma unroll
        for (int h = 0; h < 2; h++)
            tg[mi][h] = targets[bm + wm * 64 + mi * 16 + (lane >> 2) + h * 8];

    float rs[4][2];
#pragma unroll
    for (int mi = 0; mi < 4; mi++) { rs[mi][0] = 0.f; rs[mi][1] = 0.f; }

#pragma unroll
    for (int ni = 0; ni < 8; ni++) {
#pragma unroll
        for (int j = 0; j < 2; j++) {
            int col = bn + wn * 64 + ni * 8 + ((lane & 3) << 1) + j;
            int sid = sampled[col];
            float bc = g_bcorr[col];
#pragma unroll
            for (int mi = 0; mi < 4; mi++) {
#pragma unroll
                for (int h = 0; h < 2; h++) {
                    if (sid != tg[mi][h])
                        rs[mi][h] += __expf(acc[mi][ni][h * 2 + j] + bc);
                }
            }
        }
    }

#pragma unroll
    for (int mi = 0; mi < 4; mi++) {
#pragma unroll
        for (int h = 0; h < 2; h++) {
            float v = rs[mi][h];
            v += __shfl_xor_sync(0xffffffffu, v, 1);
            v += __shfl_xor_sync(0xffffffffu, v, 2);
            if ((lane & 3) == 0)
                atomicAdd(&srow[wm * 64 + mi * 16 + (lane >> 2) + h * 8], v);
        }
    }
    __syncthreads();
    atomicAdd(&g_rowsum[bm + tid], srow[tid]);
}

// ---------------- finalize: parallel per-example loss + mean ----------------
__global__ void finalize_kernel(float* __restrict__ out) {
    __shared__ double sh[4];
    const int n = blockIdx.x * 128 + threadIdx.x;
    const int lane = threadIdx.x & 31, wid = threadIdx.x >> 5;

    float t = g_true[n];
    double local = (double)(logf(g_rowsum[n] + expf(t)) - t);
#pragma unroll
    for (int o = 16; o; o >>= 1) local += __shfl_down_sync(0xffffffffu, local, o);
    if (lane == 0) sh[wid] = local;
    __syncthreads();
    if (threadIdx.x == 0) {
        double s = sh[0] + sh[1] + sh[2] + sh[3];
        g_part[blockIdx.x] = s;
        __threadfence();
        unsigned int r = atomicAdd(&g_tick, 1u);
        if (r == 63u) {
            double tot = 0.0;
#pragma unroll 8
            for (int i = 0; i < 64; ++i) tot += g_part[i];
            out[0] = (float)(tot / (double)PN);
        }
    }
}

// ---------------- entry ----------------
extern "C" void kernel_launch(void* const* d_in, const int* in_sizes, int n_in,
                              void* d_out, int out_size) {
    const float* inputs  = (const float*)d_in[0];
    const int*   targets = (const int*)d_in[1];
    const int*   sampled = (const int*)d_in[2];
    const float* kern    = (const float*)d_in[3];
    const float* bias    = (const float*)d_in[4];
    float* out = (float*)d_out;

    static int smem_set = 0;
    if (!smem_set) {
        cudaFuncSetAttribute(gemm_exp_kernel,
                             cudaFuncAttributeMaxDynamicSharedMemorySize, SMEM_BYTES);
        smem_set = 1;
    }

    prep_kernel<<<2048, 256>>>(inputs, sampled, targets, kern, bias);

    dim3 grid(PS / 128, PN / 128);
    gemm_exp_kernel<<<grid, 128, SMEM_BYTES>>>(targets, sampled);

    finalize_kernel<<<64, 128>>>(out);
}